// round 1
// baseline (speedup 1.0000x reference)
#include <cuda_runtime.h>
#include <cuda_bf16.h>
#include <math.h>

// Problem constants
#define BATCH   4
#define SEQ     2048
#define DMODEL  1024
#define NHEAD   16
#define HDIM    64
#define ROWS    (BATCH * SEQ)          // 8192

// -------- scratch (static device globals; no allocation allowed) ----------
__device__ float g_Q[ROWS * DMODEL];
__device__ float g_K[ROWS * DMODEL];
__device__ float g_V[ROWS * DMODEL];
__device__ float g_AO[ROWS * DMODEL];  // attention output (pre-Wo)

// ===========================================================================
// GEMM:  C[M,N] = A[M,K] @ W[N,K]^T + bias[N] (+ resid[M,N] if non-null)
// BM=BN=128, BK=16, 256 threads, 8x8 per thread.
// ===========================================================================
__global__ void __launch_bounds__(256)
gemm_bias_kernel(const float* __restrict__ A, const float* __restrict__ W,
                 const float* __restrict__ bias, const float* __restrict__ resid,
                 float* __restrict__ C, int M, int N, int K)
{
    __shared__ float As[16][128];
    __shared__ float Ws[16][128];

    const int tid = threadIdx.x;
    const int bm = blockIdx.y * 128;
    const int bn = blockIdx.x * 128;
    const int tr = tid >> 4;      // 0..15  (M groups of 8)
    const int tc = tid & 15;      // 0..15  (N groups of 8)

    float acc[8][8];
#pragma unroll
    for (int i = 0; i < 8; i++)
#pragma unroll
        for (int j = 0; j < 8; j++) acc[i][j] = 0.f;

    // loader mapping: each thread loads 8 consecutive k-floats of one row
    const int lrow = tid >> 1;          // 0..127
    const int lcol = (tid & 1) * 8;     // 0 or 8
    const float* Aload = A + (size_t)(bm + lrow) * K + lcol;
    const float* Wload = W + (size_t)(bn + lrow) * K + lcol;

    for (int k0 = 0; k0 < K; k0 += 16) {
        float4 a0 = *(const float4*)(Aload + k0);
        float4 a1 = *(const float4*)(Aload + k0 + 4);
        float4 w0 = *(const float4*)(Wload + k0);
        float4 w1 = *(const float4*)(Wload + k0 + 4);
        __syncthreads();   // previous tile's compute done before overwrite
        As[lcol + 0][lrow] = a0.x; As[lcol + 1][lrow] = a0.y;
        As[lcol + 2][lrow] = a0.z; As[lcol + 3][lrow] = a0.w;
        As[lcol + 4][lrow] = a1.x; As[lcol + 5][lrow] = a1.y;
        As[lcol + 6][lrow] = a1.z; As[lcol + 7][lrow] = a1.w;
        Ws[lcol + 0][lrow] = w0.x; Ws[lcol + 1][lrow] = w0.y;
        Ws[lcol + 2][lrow] = w0.z; Ws[lcol + 3][lrow] = w0.w;
        Ws[lcol + 4][lrow] = w1.x; Ws[lcol + 5][lrow] = w1.y;
        Ws[lcol + 6][lrow] = w1.z; Ws[lcol + 7][lrow] = w1.w;
        __syncthreads();

#pragma unroll
        for (int k = 0; k < 16; k++) {
            float a[8], b[8];
            float4 t0 = *(const float4*)&As[k][tr * 8];
            float4 t1 = *(const float4*)&As[k][tr * 8 + 4];
            a[0] = t0.x; a[1] = t0.y; a[2] = t0.z; a[3] = t0.w;
            a[4] = t1.x; a[5] = t1.y; a[6] = t1.z; a[7] = t1.w;
            float4 u0 = *(const float4*)&Ws[k][tc * 8];
            float4 u1 = *(const float4*)&Ws[k][tc * 8 + 4];
            b[0] = u0.x; b[1] = u0.y; b[2] = u0.z; b[3] = u0.w;
            b[4] = u1.x; b[5] = u1.y; b[6] = u1.z; b[7] = u1.w;
#pragma unroll
            for (int i = 0; i < 8; i++)
#pragma unroll
                for (int j = 0; j < 8; j++)
                    acc[i][j] += a[i] * b[j];
        }
    }

    // epilogue
    float bs[8];
    {
        float4 b0 = *(const float4*)(bias + bn + tc * 8);
        float4 b1 = *(const float4*)(bias + bn + tc * 8 + 4);
        bs[0] = b0.x; bs[1] = b0.y; bs[2] = b0.z; bs[3] = b0.w;
        bs[4] = b1.x; bs[5] = b1.y; bs[6] = b1.z; bs[7] = b1.w;
    }
#pragma unroll
    for (int i = 0; i < 8; i++) {
        const int row = bm + tr * 8 + i;
        float* cp = C + (size_t)row * N + bn + tc * 8;
        float v[8];
#pragma unroll
        for (int j = 0; j < 8; j++) v[j] = acc[i][j] + bs[j];
        if (resid) {
            const float* rp = resid + (size_t)row * N + bn + tc * 8;
            float4 r0 = *(const float4*)rp;
            float4 r1 = *(const float4*)(rp + 4);
            v[0] += r0.x; v[1] += r0.y; v[2] += r0.z; v[3] += r0.w;
            v[4] += r1.x; v[5] += r1.y; v[6] += r1.z; v[7] += r1.w;
        }
        float4 o0 = make_float4(v[0], v[1], v[2], v[3]);
        float4 o1 = make_float4(v[4], v[5], v[6], v[7]);
        *(float4*)cp = o0;
        *(float4*)(cp + 4) = o1;
    }
}

// ===========================================================================
// Flash-style attention: 128 threads/block, 1 query row per thread.
// grid = (SEQ/128, BATCH*NHEAD).  q[64], o[64] in registers; K/V tiles of 64
// keys staged in smem, broadcast float4 reads; online softmax with rare
// rescale branch.
// ===========================================================================
__global__ void __launch_bounds__(128)
attn_kernel(const float* __restrict__ Q, const float* __restrict__ K,
            const float* __restrict__ V, float* __restrict__ O)
{
    __shared__ float4 Ks4[64 * 16];
    __shared__ float4 Vs4[64 * 16];

    const int tid = threadIdx.x;
    const int qtile = blockIdx.x;            // 0..15
    const int bh = blockIdx.y;               // 0..63
    const int b = bh >> 4, h = bh & 15;
    const int qrow = qtile * 128 + tid;      // s index

    const float* qptr = Q + ((size_t)(b * SEQ + qrow)) * DMODEL + h * HDIM;
    float q[64], o[64];
#pragma unroll
    for (int i = 0; i < 16; i++) {
        float4 t = ((const float4*)qptr)[i];
        q[4 * i] = t.x; q[4 * i + 1] = t.y; q[4 * i + 2] = t.z; q[4 * i + 3] = t.w;
    }
#pragma unroll
    for (int i = 0; i < 64; i++) o[i] = 0.f;

    float m = -1e30f, l = 0.f;
    const float* kbase = K + (size_t)b * SEQ * DMODEL + h * HDIM;
    const float* vbase = V + (size_t)b * SEQ * DMODEL + h * HDIM;

    for (int j0 = 0; j0 < SEQ; j0 += 64) {
        __syncthreads();
        for (int i = tid; i < 64 * 16; i += 128) {
            const int r = i >> 4, c = i & 15;
            Ks4[i] = ((const float4*)(kbase + (size_t)(j0 + r) * DMODEL))[c];
            Vs4[i] = ((const float4*)(vbase + (size_t)(j0 + r) * DMODEL))[c];
        }
        __syncthreads();

        for (int j = 0; j < 64; j++) {
            float s = 0.f;
#pragma unroll
            for (int d4 = 0; d4 < 16; d4++) {
                float4 k4 = Ks4[j * 16 + d4];
                s += q[4 * d4] * k4.x + q[4 * d4 + 1] * k4.y
                   + q[4 * d4 + 2] * k4.z + q[4 * d4 + 3] * k4.w;
            }
            s *= 0.125f;   // 1/sqrt(64)
            if (s > m) {
                float c = __expf(m - s);
                l *= c;
#pragma unroll
                for (int d = 0; d < 64; d++) o[d] *= c;
                m = s;
            }
            float p = __expf(s - m);
            l += p;
#pragma unroll
            for (int d4 = 0; d4 < 16; d4++) {
                float4 v4 = Vs4[j * 16 + d4];
                o[4 * d4]     += p * v4.x;
                o[4 * d4 + 1] += p * v4.y;
                o[4 * d4 + 2] += p * v4.z;
                o[4 * d4 + 3] += p * v4.w;
            }
        }
    }

    const float inv = 1.f / l;
    float* optr = O + ((size_t)(b * SEQ + qrow)) * DMODEL + h * HDIM;
#pragma unroll
    for (int i = 0; i < 16; i++) {
        float4 t = make_float4(o[4 * i] * inv, o[4 * i + 1] * inv,
                               o[4 * i + 2] * inv, o[4 * i + 3] * inv);
        ((float4*)optr)[i] = t;
    }
}

// ===========================================================================
// LayerNorm over rows of 1024; one block (256 threads, float4/thread) per row.
// ===========================================================================
__global__ void __launch_bounds__(256)
ln_kernel(const float* __restrict__ Y, const float* __restrict__ gamma,
          const float* __restrict__ beta, float* __restrict__ out)
{
    __shared__ float red[8];
    __shared__ float bcast;

    const int row = blockIdx.x;
    const int tid = threadIdx.x;
    const float4 v = ((const float4*)(Y + (size_t)row * DMODEL))[tid];

    float s = v.x + v.y + v.z + v.w;
#pragma unroll
    for (int off = 16; off; off >>= 1) s += __shfl_xor_sync(0xffffffffu, s, off);
    if ((tid & 31) == 0) red[tid >> 5] = s;
    __syncthreads();
    if (tid == 0) {
        float t = 0.f;
#pragma unroll
        for (int i = 0; i < 8; i++) t += red[i];
        bcast = t * (1.f / 1024.f);
    }
    __syncthreads();
    const float mean = bcast;

    const float dx = v.x - mean, dy = v.y - mean, dz = v.z - mean, dw = v.w - mean;
    float ss = dx * dx + dy * dy + dz * dz + dw * dw;
#pragma unroll
    for (int off = 16; off; off >>= 1) ss += __shfl_xor_sync(0xffffffffu, ss, off);
    __syncthreads();    // protect red[] reuse
    if ((tid & 31) == 0) red[tid >> 5] = ss;
    __syncthreads();
    if (tid == 0) {
        float t = 0.f;
#pragma unroll
        for (int i = 0; i < 8; i++) t += red[i];
        bcast = rsqrtf(t * (1.f / 1024.f) + 1e-12f);
    }
    __syncthreads();
    const float inv = bcast;

    const float4 g = ((const float4*)gamma)[tid];
    const float4 bb = ((const float4*)beta)[tid];
    float4 o = make_float4(dx * inv * g.x + bb.x, dy * inv * g.y + bb.y,
                           dz * inv * g.z + bb.z, dw * inv * g.w + bb.w);
    ((float4*)(out + (size_t)row * DMODEL))[tid] = o;
}

// ===========================================================================
extern "C" void kernel_launch(void* const* d_in, const int* in_sizes, int n_in,
                              void* d_out, int out_size)
{
    const float* X     = (const float*)d_in[0];
    const float* Wq    = (const float*)d_in[1];
    const float* bq    = (const float*)d_in[2];
    const float* Wk    = (const float*)d_in[3];
    const float* bk    = (const float*)d_in[4];
    const float* Wv    = (const float*)d_in[5];
    const float* bv    = (const float*)d_in[6];
    const float* Wo    = (const float*)d_in[7];
    const float* bo    = (const float*)d_in[8];
    const float* gamma = (const float*)d_in[9];
    const float* beta  = (const float*)d_in[10];
    float* out = (float*)d_out;

    float *Qb, *Kb, *Vb, *Ob;
    cudaGetSymbolAddress((void**)&Qb, g_Q);
    cudaGetSymbolAddress((void**)&Kb, g_K);
    cudaGetSymbolAddress((void**)&Vb, g_V);
    cudaGetSymbolAddress((void**)&Ob, g_AO);

    dim3 gg(DMODEL / 128, ROWS / 128);   // (8, 64)

    gemm_bias_kernel<<<gg, 256>>>(X, Wq, bq, nullptr, Qb, ROWS, DMODEL, DMODEL);
    gemm_bias_kernel<<<gg, 256>>>(X, Wk, bk, nullptr, Kb, ROWS, DMODEL, DMODEL);
    gemm_bias_kernel<<<gg, 256>>>(X, Wv, bv, nullptr, Vb, ROWS, DMODEL, DMODEL);

    attn_kernel<<<dim3(SEQ / 128, BATCH * NHEAD), 128>>>(Qb, Kb, Vb, Ob);

    // Y = AO @ Wo^T + bo + X   (into Qb, reused as Y scratch)
    gemm_bias_kernel<<<gg, 256>>>(Ob, Wo, bo, X, Qb, ROWS, DMODEL, DMODEL);

    ln_kernel<<<ROWS, 256>>>(Qb, gamma, beta, out);
}

// round 3
// speedup vs baseline: 1.3959x; 1.3959x over previous
#include <cuda_runtime.h>
#include <cuda_bf16.h>
#include <math.h>
#include <stdint.h>

// Problem constants
#define BATCH   4
#define SEQ     2048
#define DMODEL  1024
#define NHEAD   16
#define HDIM    64
#define ROWS    (BATCH * SEQ)          // 8192

// tcgen05 only exists in the arch-specific (sm_103a/sm_100a) device pass.
// The harness also runs a base compute_103 ptxas pass where these mnemonics
// are illegal — that pass compiles the SIMT fallback below instead.
#if defined(__CUDA_ARCH_FEAT_SM103_ALL) || defined(__CUDA_ARCH_FEAT_SM100_ALL)
#define HAS_TCGEN05 1
#else
#define HAS_TCGEN05 0
#endif

// -------- scratch (static device globals; no allocation allowed) ----------
__device__ float g_Q[ROWS * DMODEL];
__device__ float g_K[ROWS * DMODEL];
__device__ float g_V[ROWS * DMODEL];
__device__ float g_AO[ROWS * DMODEL];  // attention output (pre-Wo)

__device__ __nv_bfloat16 g_Ahi[ROWS * DMODEL];   // split of X / AO (activation operand)
__device__ __nv_bfloat16 g_Alo[ROWS * DMODEL];
__device__ __nv_bfloat16 g_Whi[DMODEL * DMODEL]; // split of current weight
__device__ __nv_bfloat16 g_Wlo[DMODEL * DMODEL];

// ===========================================================================
// PTX helpers
// ===========================================================================
__device__ __forceinline__ uint32_t smem_u32(const void* p) {
    uint32_t a;
    asm("{ .reg .u64 t; cvta.to.shared.u64 t, %1; cvt.u32.u64 %0, t; }" : "=r"(a) : "l"(p));
    return a;
}
__device__ __forceinline__ uint32_t elect_one() {
    uint32_t p;
    asm volatile("{ .reg .pred q; elect.sync _|q, 0xFFFFFFFF; selp.b32 %0, 1, 0, q; }" : "=r"(p));
    return p;
}
__device__ __forceinline__ void mbar_init(uint32_t mbar, uint32_t cnt) {
    asm volatile("mbarrier.init.shared.b64 [%0], %1;" :: "r"(mbar), "r"(cnt) : "memory");
}
__device__ __forceinline__ void mbar_wait(uint32_t mbar, uint32_t parity) {
    uint32_t done;
    asm volatile("{ .reg .pred p; mbarrier.try_wait.parity.acquire.cta.shared::cta.b64 p, [%1], %2; selp.b32 %0, 1, 0, p; }"
                 : "=r"(done) : "r"(mbar), "r"(parity) : "memory");
    while (!done) {
        asm volatile("{ .reg .pred p; mbarrier.try_wait.parity.acquire.cta.shared::cta.b64 p, [%1], %2, 0x989680; selp.b32 %0, 1, 0, p; }"
                     : "=r"(done) : "r"(mbar), "r"(parity) : "memory");
    }
}
__device__ __forceinline__ void fence_proxy_async_shared() { asm volatile("fence.proxy.async.shared::cta;" ::: "memory"); }

// packed f32x2 helpers (legal on base sm_103 target)
__device__ __forceinline__ unsigned long long pk2(float lo, float hi) {
    unsigned long long r;
    asm("mov.b64 %0, {%1, %2};" : "=l"(r) : "r"(__float_as_uint(lo)), "r"(__float_as_uint(hi)));
    return r;
}
__device__ __forceinline__ void unpk2(unsigned long long v, float& lo, float& hi) {
    uint32_t a, b;
    asm("mov.b64 {%0, %1}, %2;" : "=r"(a), "=r"(b) : "l"(v));
    lo = __uint_as_float(a); hi = __uint_as_float(b);
}
__device__ __forceinline__ unsigned long long ffma2(unsigned long long a, unsigned long long b, unsigned long long c) {
    unsigned long long d;
    asm("fma.rn.f32x2 %0, %1, %2, %3;" : "=l"(d) : "l"(a), "l"(b), "l"(c));
    return d;
}
__device__ __forceinline__ unsigned long long fmul2(unsigned long long a, unsigned long long b) {
    unsigned long long d;
    asm("mul.rn.f32x2 %0, %1, %2;" : "=l"(d) : "l"(a), "l"(b));
    return d;
}

// SW128 K-major smem descriptor (LBO=1, SBO=64, version=1, layout=SW128)
static constexpr uint64_t DESC_BASE_SW128 =
    (uint64_t(2) << 61) | (uint64_t(1) << 46) | (uint64_t(64) << 32) | (uint64_t(1) << 16);
__device__ __forceinline__ uint64_t make_desc(uint32_t addr) {
    return DESC_BASE_SW128 | ((uint64_t)(addr >> 4) & 0x3FFF);
}

// ===========================================================================
// fp32 -> (bf16 hi, bf16 lo) split, vectorized by 4
// ===========================================================================
__global__ void __launch_bounds__(256)
split_kernel(const float* __restrict__ x, __nv_bfloat16* __restrict__ hi,
             __nv_bfloat16* __restrict__ lo, int n4)
{
    int i = blockIdx.x * blockDim.x + threadIdx.x;
    if (i >= n4) return;
    float4 v = ((const float4*)x)[i];
    __nv_bfloat16 hx = __float2bfloat16_rn(v.x);
    __nv_bfloat16 hy = __float2bfloat16_rn(v.y);
    __nv_bfloat16 hz = __float2bfloat16_rn(v.z);
    __nv_bfloat16 hw = __float2bfloat16_rn(v.w);
    __nv_bfloat16 lx = __float2bfloat16_rn(v.x - __bfloat162float(hx));
    __nv_bfloat16 ly = __float2bfloat16_rn(v.y - __bfloat162float(hy));
    __nv_bfloat16 lz = __float2bfloat16_rn(v.z - __bfloat162float(hz));
    __nv_bfloat16 lw = __float2bfloat16_rn(v.w - __bfloat162float(hw));
    ((__nv_bfloat162*)hi)[2 * i]     = __nv_bfloat162(hx, hy);
    ((__nv_bfloat162*)hi)[2 * i + 1] = __nv_bfloat162(hz, hw);
    ((__nv_bfloat162*)lo)[2 * i]     = __nv_bfloat162(lx, ly);
    ((__nv_bfloat162*)lo)[2 * i + 1] = __nv_bfloat162(lz, lw);
}

// ===========================================================================
// GEMM: C[8192,1024] = (Ahi+Alo)[8192,1024] @ (Whi+Wlo)[1024,1024]^T + bias
//       (+resid).  tcgen05 split-bf16 3-product path when available,
//       SIMT fp32 fallback otherwise.  128 threads/CTA, tile 128x128.
// ===========================================================================
#define GM_K        DMODEL
#define CHUNK       64                       // bf16 k per chunk
#define NCHUNK      (GM_K / CHUNK)           // 16
#define TILE_B      (128 * 128)              // 16KB per bf16 tile (128 rows x 128B)
#define OFF_AHI     1024
#define OFF_ALO     (OFF_AHI + TILE_B)
#define OFF_WHI     (OFF_ALO + TILE_B)
#define OFF_WLO     (OFF_WHI + TILE_B)
#define GEMM_SMEM   (OFF_WLO + TILE_B)       // 66560

static constexpr uint32_t GEMM_IDESC =
    (1u << 4) | (1u << 7) | (1u << 10) | ((128u / 8u) << 17) | ((128u / 16u) << 24);

#if HAS_TCGEN05
__device__ __forceinline__ void mma_bf16_ss(uint32_t d_tmem, uint64_t a_desc, uint64_t b_desc,
                                            uint32_t idesc, uint32_t enable) {
    asm volatile(
        "{ .reg .pred p; setp.ne.u32 p, %5, 0;\n\t"
        "tcgen05.mma.cta_group::1.kind::f16 [%0], %1, %2, %3, {%4, %4, %4, %4}, p; }"
        :: "r"(d_tmem), "l"(a_desc), "l"(b_desc), "r"(idesc), "r"(0u), "r"(enable)
        : "memory");
}
#define TCGEN05_LD_X32(r, tmem_addr) \
    asm volatile( \
        "tcgen05.ld.sync.aligned.32x32b.x32.b32 " \
        "{%0, %1, %2, %3, %4, %5, %6, %7, " \
        " %8, %9, %10, %11, %12, %13, %14, %15, " \
        " %16, %17, %18, %19, %20, %21, %22, %23, " \
        " %24, %25, %26, %27, %28, %29, %30, %31}, [%32];" \
        : "=r"((r)[0]),  "=r"((r)[1]),  "=r"((r)[2]),  "=r"((r)[3]), \
          "=r"((r)[4]),  "=r"((r)[5]),  "=r"((r)[6]),  "=r"((r)[7]), \
          "=r"((r)[8]),  "=r"((r)[9]),  "=r"((r)[10]), "=r"((r)[11]), \
          "=r"((r)[12]), "=r"((r)[13]), "=r"((r)[14]), "=r"((r)[15]), \
          "=r"((r)[16]), "=r"((r)[17]), "=r"((r)[18]), "=r"((r)[19]), \
          "=r"((r)[20]), "=r"((r)[21]), "=r"((r)[22]), "=r"((r)[23]), \
          "=r"((r)[24]), "=r"((r)[25]), "=r"((r)[26]), "=r"((r)[27]), \
          "=r"((r)[28]), "=r"((r)[29]), "=r"((r)[30]), "=r"((r)[31]) \
        : "r"(tmem_addr))
#endif

__global__ void __launch_bounds__(128)
gemm_tc_kernel(const __nv_bfloat16* __restrict__ Ahi, const __nv_bfloat16* __restrict__ Alo,
               const __nv_bfloat16* __restrict__ Whi, const __nv_bfloat16* __restrict__ Wlo,
               const float* __restrict__ bias, const float* __restrict__ resid,
               float* __restrict__ C)
{
    extern __shared__ char smem[];
    const int tid = threadIdx.x;
    const int bn = blockIdx.x * 128;
    const int bm = blockIdx.y * 128;

#if HAS_TCGEN05
    const uint32_t sbase = smem_u32(smem);
    const uint32_t mbar = sbase + 16;
    const int wid = tid >> 5, lid = tid & 31;

    if (wid == 0)
        asm volatile("tcgen05.alloc.cta_group::1.sync.aligned.shared::cta.b32 [%0], %1;"
                     :: "r"(sbase), "r"(128u) : "memory");
    if (tid == 0) mbar_init(mbar, 1);
    __syncthreads();
    uint32_t tmem;
    asm volatile("ld.shared.b32 %0, [%1];" : "=r"(tmem) : "r"(sbase));

    // loader mapping: seg = tid&7 (16B units along k), rows tid>>3 + 16*s
    const int seg = tid & 7;
    const int r0 = tid >> 3;

    for (int c = 0; c < NCHUNK; ++c) {
        if (c > 0) mbar_wait(mbar, (c - 1) & 1);
        __syncthreads();

        const int kc = c * CHUNK;
#pragma unroll
        for (int s = 0; s < 8; ++s) {
            const int row = s * 16 + r0;
            uint32_t boff = (uint32_t)row * 128u + (uint32_t)seg * 16u;
            uint32_t sw = boff ^ ((boff >> 3) & 0x70u);
            const uint4* ga  = (const uint4*)(Ahi + (size_t)(bm + row) * GM_K + kc);
            const uint4* gal = (const uint4*)(Alo + (size_t)(bm + row) * GM_K + kc);
            const uint4* gw  = (const uint4*)(Whi + (size_t)(bn + row) * GM_K + kc);
            const uint4* gwl = (const uint4*)(Wlo + (size_t)(bn + row) * GM_K + kc);
            *(uint4*)(smem + OFF_AHI + sw) = ga[seg];
            *(uint4*)(smem + OFF_ALO + sw) = gal[seg];
            *(uint4*)(smem + OFF_WHI + sw) = gw[seg];
            *(uint4*)(smem + OFF_WLO + sw) = gwl[seg];
        }
        fence_proxy_async_shared();
        __syncthreads();

        if (wid == 0 && elect_one()) {
            const uint64_t dah = make_desc(sbase + OFF_AHI);
            const uint64_t dal = make_desc(sbase + OFF_ALO);
            const uint64_t dwh = make_desc(sbase + OFF_WHI);
            const uint64_t dwl = make_desc(sbase + OFF_WLO);
#pragma unroll
            for (int k = 0; k < 4; ++k)
                mma_bf16_ss(tmem, dah + k * 2, dwh + k * 2, GEMM_IDESC, (c > 0) || (k > 0));
#pragma unroll
            for (int k = 0; k < 4; ++k)
                mma_bf16_ss(tmem, dal + k * 2, dwh + k * 2, GEMM_IDESC, 1u);
#pragma unroll
            for (int k = 0; k < 4; ++k)
                mma_bf16_ss(tmem, dah + k * 2, dwl + k * 2, GEMM_IDESC, 1u);
            asm volatile("tcgen05.commit.cta_group::1.mbarrier::arrive::one.shared::cluster.b64 [%0];"
                         :: "r"(mbar) : "memory");
        }
    }

    mbar_wait(mbar, (NCHUNK - 1) & 1);
    asm volatile("tcgen05.fence::after_thread_sync;" ::: "memory");

    // epilogue: warp w owns rows bm + w*32 + lid (lane = row within subpartition)
    const int row = bm + wid * 32 + lid;
    float* crow = C + (size_t)row * DMODEL + bn;
    const float* rrow = resid ? resid + (size_t)row * DMODEL + bn : nullptr;
#pragma unroll
    for (int c0 = 0; c0 < 128; c0 += 32) {
        uint32_t dr[32];
        TCGEN05_LD_X32(dr, tmem + c0);
        asm volatile("tcgen05.wait::ld.sync.aligned;" ::: "memory");
#pragma unroll
        for (int j = 0; j < 32; j += 4) {
            float4 v;
            v.x = __uint_as_float(dr[j + 0]) + bias[bn + c0 + j + 0];
            v.y = __uint_as_float(dr[j + 1]) + bias[bn + c0 + j + 1];
            v.z = __uint_as_float(dr[j + 2]) + bias[bn + c0 + j + 2];
            v.w = __uint_as_float(dr[j + 3]) + bias[bn + c0 + j + 3];
            if (rrow) {
                float4 r = *(const float4*)(rrow + c0 + j);
                v.x += r.x; v.y += r.y; v.z += r.z; v.w += r.w;
            }
            *(float4*)(crow + c0 + j) = v;
        }
    }
    asm volatile("tcgen05.fence::before_thread_sync;" ::: "memory");
    __syncthreads();
    if (wid == 0) {
        asm volatile("tcgen05.relinquish_alloc_permit.cta_group::1.sync.aligned;" ::: "memory");
        asm volatile("tcgen05.dealloc.cta_group::1.sync.aligned.b32 %0, %1;" :: "r"(tmem), "r"(128u));
    }

#else  // ---------------- SIMT fallback (base-target pass) ----------------
    float* As = (float*)smem;             // [16][128]
    float* Ws = (float*)(smem + 8192);    // [16][128]
    const int tr = tid >> 4;              // 0..7  -> 16 rows each
    const int tc = tid & 15;              // 0..15 -> 8 cols each

    float acc[16][8];
#pragma unroll
    for (int i = 0; i < 16; i++)
#pragma unroll
        for (int j = 0; j < 8; j++) acc[i][j] = 0.f;

    for (int k0 = 0; k0 < GM_K; k0 += 16) {
        __syncthreads();
        // thread tid loads row tid, 16 k-values (8 bf162 per array)
        {
            const __nv_bfloat162* ah  = (const __nv_bfloat162*)(Ahi + (size_t)(bm + tid) * GM_K + k0);
            const __nv_bfloat162* al  = (const __nv_bfloat162*)(Alo + (size_t)(bm + tid) * GM_K + k0);
            const __nv_bfloat162* wh  = (const __nv_bfloat162*)(Whi + (size_t)(bn + tid) * GM_K + k0);
            const __nv_bfloat162* wl  = (const __nv_bfloat162*)(Wlo + (size_t)(bn + tid) * GM_K + k0);
#pragma unroll
            for (int p = 0; p < 8; p++) {
                float2 h = __bfloat1622float2(ah[p]);
                float2 l = __bfloat1622float2(al[p]);
                As[(2 * p) * 128 + tid]     = h.x + l.x;
                As[(2 * p + 1) * 128 + tid] = h.y + l.y;
                float2 wh2 = __bfloat1622float2(wh[p]);
                float2 wl2 = __bfloat1622float2(wl[p]);
                Ws[(2 * p) * 128 + tid]     = wh2.x + wl2.x;
                Ws[(2 * p + 1) * 128 + tid] = wh2.y + wl2.y;
            }
        }
        __syncthreads();
#pragma unroll
        for (int k = 0; k < 16; k++) {
            float b[8];
#pragma unroll
            for (int j = 0; j < 8; j++) b[j] = Ws[k * 128 + tc * 8 + j];
#pragma unroll
            for (int i = 0; i < 16; i++) {
                float a = As[k * 128 + tr * 16 + i];
#pragma unroll
                for (int j = 0; j < 8; j++) acc[i][j] += a * b[j];
            }
        }
    }

#pragma unroll
    for (int i = 0; i < 16; i++) {
        const int row = bm + tr * 16 + i;
        float* cp = C + (size_t)row * DMODEL + bn + tc * 8;
#pragma unroll
        for (int j = 0; j < 8; j++) {
            float v = acc[i][j] + bias[bn + tc * 8 + j];
            if (resid) v += resid[(size_t)row * DMODEL + bn + tc * 8 + j];
            cp[j] = v;
        }
    }
#endif
}

// ===========================================================================
// Flash-style attention with packed fma.rn.f32x2 (fp32-exact per lane).
// 128 threads/block, 1 query row per thread.
// ===========================================================================
__global__ void __launch_bounds__(128)
attn_kernel(const float* __restrict__ Q, const float* __restrict__ K,
            const float* __restrict__ V, float* __restrict__ O)
{
    __shared__ float4 Ks4[64 * 16];
    __shared__ float4 Vs4[64 * 16];

    const int tid = threadIdx.x;
    const int qtile = blockIdx.x;            // 0..15
    const int bh = blockIdx.y;               // 0..63
    const int b = bh >> 4, h = bh & 15;
    const int qrow = qtile * 128 + tid;

    const float* qptr = Q + ((size_t)(b * SEQ + qrow)) * DMODEL + h * HDIM;
    unsigned long long qp[32], op[32];
#pragma unroll
    for (int i = 0; i < 16; i++) {
        float4 t = ((const float4*)qptr)[i];
        qp[2 * i]     = pk2(t.x, t.y);
        qp[2 * i + 1] = pk2(t.z, t.w);
    }
#pragma unroll
    for (int i = 0; i < 32; i++) op[i] = 0ull;

    float m = -1e30f, l = 0.f;
    const float* kbase = K + (size_t)b * SEQ * DMODEL + h * HDIM;
    const float* vbase = V + (size_t)b * SEQ * DMODEL + h * HDIM;
    const ulonglong2* Ku = (const ulonglong2*)Ks4;
    const ulonglong2* Vu = (const ulonglong2*)Vs4;

    for (int j0 = 0; j0 < SEQ; j0 += 64) {
        __syncthreads();
        for (int i = tid; i < 64 * 16; i += 128) {
            const int r = i >> 4, cc = i & 15;
            Ks4[i] = ((const float4*)(kbase + (size_t)(j0 + r) * DMODEL))[cc];
            Vs4[i] = ((const float4*)(vbase + (size_t)(j0 + r) * DMODEL))[cc];
        }
        __syncthreads();

        for (int j = 0; j < 64; j++) {
            unsigned long long a0 = 0ull, a1 = 0ull;
#pragma unroll
            for (int d4 = 0; d4 < 16; d4++) {
                ulonglong2 kk = Ku[j * 16 + d4];
                a0 = ffma2(qp[2 * d4], kk.x, a0);
                a1 = ffma2(qp[2 * d4 + 1], kk.y, a1);
            }
            float sx, sy, sz, sw;
            unpk2(a0, sx, sy); unpk2(a1, sz, sw);
            float s = ((sx + sy) + (sz + sw)) * 0.125f;

            if (s > m) {
                float c = __expf(m - s);
                l *= c;
                unsigned long long c2 = pk2(c, c);
#pragma unroll
                for (int i = 0; i < 32; i++) op[i] = fmul2(op[i], c2);
                m = s;
            }
            float p = __expf(s - m);
            l += p;
            unsigned long long p2 = pk2(p, p);
#pragma unroll
            for (int d4 = 0; d4 < 16; d4++) {
                ulonglong2 vv = Vu[j * 16 + d4];
                op[2 * d4]     = ffma2(p2, vv.x, op[2 * d4]);
                op[2 * d4 + 1] = ffma2(p2, vv.y, op[2 * d4 + 1]);
            }
        }
    }

    const float inv = 1.f / l;
    float* optr = O + ((size_t)(b * SEQ + qrow)) * DMODEL + h * HDIM;
#pragma unroll
    for (int i = 0; i < 16; i++) {
        float ox, oy, oz, ow;
        unpk2(op[2 * i], ox, oy); unpk2(op[2 * i + 1], oz, ow);
        ((float4*)optr)[i] = make_float4(ox * inv, oy * inv, oz * inv, ow * inv);
    }
}

// ===========================================================================
// LayerNorm over rows of 1024; one block (256 threads, float4/thread) per row.
// ===========================================================================
__global__ void __launch_bounds__(256)
ln_kernel(const float* __restrict__ Y, const float* __restrict__ gamma,
          const float* __restrict__ beta, float* __restrict__ out)
{
    __shared__ float red[8];
    __shared__ float bcast;

    const int row = blockIdx.x;
    const int tid = threadIdx.x;
    const float4 v = ((const float4*)(Y + (size_t)row * DMODEL))[tid];

    float s = v.x + v.y + v.z + v.w;
#pragma unroll
    for (int off = 16; off; off >>= 1) s += __shfl_xor_sync(0xffffffffu, s, off);
    if ((tid & 31) == 0) red[tid >> 5] = s;
    __syncthreads();
    if (tid == 0) {
        float t = 0.f;
#pragma unroll
        for (int i = 0; i < 8; i++) t += red[i];
        bcast = t * (1.f / 1024.f);
    }
    __syncthreads();
    const float mean = bcast;

    const float dx = v.x - mean, dy = v.y - mean, dz = v.z - mean, dw = v.w - mean;
    float ss = dx * dx + dy * dy + dz * dz + dw * dw;
#pragma unroll
    for (int off = 16; off; off >>= 1) ss += __shfl_xor_sync(0xffffffffu, ss, off);
    __syncthreads();
    if ((tid & 31) == 0) red[tid >> 5] = ss;
    __syncthreads();
    if (tid == 0) {
        float t = 0.f;
#pragma unroll
        for (int i = 0; i < 8; i++) t += red[i];
        bcast = rsqrtf(t * (1.f / 1024.f) + 1e-12f);
    }
    __syncthreads();
    const float inv = bcast;

    const float4 g = ((const float4*)gamma)[tid];
    const float4 bb = ((const float4*)beta)[tid];
    float4 o = make_float4(dx * inv * g.x + bb.x, dy * inv * g.y + bb.y,
                           dz * inv * g.z + bb.z, dw * inv * g.w + bb.w);
    ((float4*)(out + (size_t)row * DMODEL))[tid] = o;
}

// ===========================================================================
extern "C" void kernel_launch(void* const* d_in, const int* in_sizes, int n_in,
                              void* d_out, int out_size)
{
    const float* X     = (const float*)d_in[0];
    const float* Wq    = (const float*)d_in[1];
    const float* bq    = (const float*)d_in[2];
    const float* Wk    = (const float*)d_in[3];
    const float* bk    = (const float*)d_in[4];
    const float* Wv    = (const float*)d_in[5];
    const float* bv    = (const float*)d_in[6];
    const float* Wo    = (const float*)d_in[7];
    const float* bo    = (const float*)d_in[8];
    const float* gamma = (const float*)d_in[9];
    const float* beta  = (const float*)d_in[10];
    float* out = (float*)d_out;

    float *Qb, *Kb, *Vb, *Ob;
    __nv_bfloat16 *Ahi, *Alo, *Whi, *Wlo;
    cudaGetSymbolAddress((void**)&Qb, g_Q);
    cudaGetSymbolAddress((void**)&Kb, g_K);
    cudaGetSymbolAddress((void**)&Vb, g_V);
    cudaGetSymbolAddress((void**)&Ob, g_AO);
    cudaGetSymbolAddress((void**)&Ahi, g_Ahi);
    cudaGetSymbolAddress((void**)&Alo, g_Alo);
    cudaGetSymbolAddress((void**)&Whi, g_Whi);
    cudaGetSymbolAddress((void**)&Wlo, g_Wlo);

    // idempotent; not stream-ordered, so safe under graph capture
    cudaFuncSetAttribute(gemm_tc_kernel, cudaFuncAttributeMaxDynamicSharedMemorySize, GEMM_SMEM);

    const int nX4 = ROWS * DMODEL / 4;      // 2M
    const int nW4 = DMODEL * DMODEL / 4;    // 256K
    dim3 gemm_grid(DMODEL / 128, ROWS / 128);   // (8, 64)

    // split activations X
    split_kernel<<<(nX4 + 255) / 256, 256>>>(X, Ahi, Alo, nX4);

    // Q = X @ Wq^T + bq
    split_kernel<<<(nW4 + 255) / 256, 256>>>(Wq, Whi, Wlo, nW4);
    gemm_tc_kernel<<<gemm_grid, 128, GEMM_SMEM>>>(Ahi, Alo, Whi, Wlo, bq, nullptr, Qb);
    // K
    split_kernel<<<(nW4 + 255) / 256, 256>>>(Wk, Whi, Wlo, nW4);
    gemm_tc_kernel<<<gemm_grid, 128, GEMM_SMEM>>>(Ahi, Alo, Whi, Wlo, bk, nullptr, Kb);
    // V
    split_kernel<<<(nW4 + 255) / 256, 256>>>(Wv, Whi, Wlo, nW4);
    gemm_tc_kernel<<<gemm_grid, 128, GEMM_SMEM>>>(Ahi, Alo, Whi, Wlo, bv, nullptr, Vb);

    // attention
    attn_kernel<<<dim3(SEQ / 128, BATCH * NHEAD), 128>>>(Qb, Kb, Vb, Ob);

    // Y = AO @ Wo^T + bo + X   (into Qb, reused as Y scratch)
    split_kernel<<<(nX4 + 255) / 256, 256>>>(Ob, Ahi, Alo, nX4);
    split_kernel<<<(nW4 + 255) / 256, 256>>>(Wo, Whi, Wlo, nW4);
    gemm_tc_kernel<<<gemm_grid, 128, GEMM_SMEM>>>(Ahi, Alo, Whi, Wlo, bo, X, Qb);

    ln_kernel<<<ROWS, 256>>>(Qb, gamma, beta, out);
}

// round 5
// speedup vs baseline: 2.9615x; 2.1216x over previous
#include <cuda_runtime.h>
#include <cuda_bf16.h>
#include <math.h>
#include <stdint.h>

// Problem constants
#define BATCH   4
#define SEQ     2048
#define DMODEL  1024
#define NHEAD   16
#define HDIM    64
#define ROWS    (BATCH * SEQ)          // 8192

// tcgen05 only exists in the arch-specific (sm_103a/sm_100a) device pass.
#if defined(__CUDA_ARCH_FEAT_SM103_ALL) || defined(__CUDA_ARCH_FEAT_SM100_ALL)
#define HAS_TCGEN05 1
#else
#define HAS_TCGEN05 0
#endif

// -------- scratch (static device globals; no allocation allowed) ----------
__device__ float g_Q[ROWS * DMODEL];
__device__ float g_K[ROWS * DMODEL];
__device__ float g_V[ROWS * DMODEL];
__device__ float g_AO[ROWS * DMODEL];  // attention output (pre-Wo)

__device__ __nv_bfloat16 g_Ahi[ROWS * DMODEL];   // split of X / Q / AO
__device__ __nv_bfloat16 g_Alo[ROWS * DMODEL];
__device__ __nv_bfloat16 g_Whi[DMODEL * DMODEL]; // split of current weight
__device__ __nv_bfloat16 g_Wlo[DMODEL * DMODEL];
__device__ __nv_bfloat16 g_Kbf[ROWS * DMODEL];   // K in bf16 (same layout)
__device__ __nv_bfloat16 g_VT[BATCH * NHEAD * HDIM * SEQ]; // V^T: [bh][d][key]

// ===========================================================================
// PTX helpers
// ===========================================================================
__device__ __forceinline__ uint32_t smem_u32(const void* p) {
    uint32_t a;
    asm("{ .reg .u64 t; cvta.to.shared.u64 t, %1; cvt.u32.u64 %0, t; }" : "=r"(a) : "l"(p));
    return a;
}
__device__ __forceinline__ uint32_t elect_one() {
    uint32_t p;
    asm volatile("{ .reg .pred q; elect.sync _|q, 0xFFFFFFFF; selp.b32 %0, 1, 0, q; }" : "=r"(p));
    return p;
}
__device__ __forceinline__ void mbar_init(uint32_t mbar, uint32_t cnt) {
    asm volatile("mbarrier.init.shared.b64 [%0], %1;" :: "r"(mbar), "r"(cnt) : "memory");
}
__device__ __forceinline__ void mbar_wait(uint32_t mbar, uint32_t parity) {
    uint32_t done;
    asm volatile("{ .reg .pred p; mbarrier.try_wait.parity.acquire.cta.shared::cta.b64 p, [%1], %2; selp.b32 %0, 1, 0, p; }"
                 : "=r"(done) : "r"(mbar), "r"(parity) : "memory");
    while (!done) {
        asm volatile("{ .reg .pred p; mbarrier.try_wait.parity.acquire.cta.shared::cta.b64 p, [%1], %2, 0x989680; selp.b32 %0, 1, 0, p; }"
                     : "=r"(done) : "r"(mbar), "r"(parity) : "memory");
    }
}
__device__ __forceinline__ void fence_proxy_async_shared() { asm volatile("fence.proxy.async.shared::cta;" ::: "memory"); }

// packed f32x2 helpers (legal on base sm_103 target)
__device__ __forceinline__ unsigned long long pk2(float lo, float hi) {
    unsigned long long r;
    asm("mov.b64 %0, {%1, %2};" : "=l"(r) : "r"(__float_as_uint(lo)), "r"(__float_as_uint(hi)));
    return r;
}
__device__ __forceinline__ void unpk2(unsigned long long v, float& lo, float& hi) {
    uint32_t a, b;
    asm("mov.b64 {%0, %1}, %2;" : "=r"(a), "=r"(b) : "l"(v));
    lo = __uint_as_float(a); hi = __uint_as_float(b);
}
__device__ __forceinline__ unsigned long long ffma2(unsigned long long a, unsigned long long b, unsigned long long c) {
    unsigned long long d;
    asm("fma.rn.f32x2 %0, %1, %2, %3;" : "=l"(d) : "l"(a), "l"(b), "l"(c));
    return d;
}
__device__ __forceinline__ unsigned long long fmul2(unsigned long long a, unsigned long long b) {
    unsigned long long d;
    asm("mul.rn.f32x2 %0, %1, %2;" : "=l"(d) : "l"(a), "l"(b));
    return d;
}

// SW128 K-major smem descriptor (LBO=1, SBO=64, version=1, layout=SW128)
static constexpr uint64_t DESC_BASE_SW128 =
    (uint64_t(2) << 61) | (uint64_t(1) << 46) | (uint64_t(64) << 32) | (uint64_t(1) << 16);
__device__ __forceinline__ uint64_t make_desc(uint32_t addr) {
    return DESC_BASE_SW128 | ((uint64_t)(addr >> 4) & 0x3FFF);
}

#if HAS_TCGEN05
__device__ __forceinline__ void mma_bf16_ss(uint32_t d_tmem, uint64_t a_desc, uint64_t b_desc,
                                            uint32_t idesc, uint32_t enable) {
    asm volatile(
        "{ .reg .pred p; setp.ne.u32 p, %5, 0;\n\t"
        "tcgen05.mma.cta_group::1.kind::f16 [%0], %1, %2, %3, {%4, %4, %4, %4}, p; }"
        :: "r"(d_tmem), "l"(a_desc), "l"(b_desc), "r"(idesc), "r"(0u), "r"(enable)
        : "memory");
}
#define TCGEN05_LD_X32(r, tmem_addr) \
    asm volatile( \
        "tcgen05.ld.sync.aligned.32x32b.x32.b32 " \
        "{%0, %1, %2, %3, %4, %5, %6, %7, " \
        " %8, %9, %10, %11, %12, %13, %14, %15, " \
        " %16, %17, %18, %19, %20, %21, %22, %23, " \
        " %24, %25, %26, %27, %28, %29, %30, %31}, [%32];" \
        : "=r"((r)[0]),  "=r"((r)[1]),  "=r"((r)[2]),  "=r"((r)[3]), \
          "=r"((r)[4]),  "=r"((r)[5]),  "=r"((r)[6]),  "=r"((r)[7]), \
          "=r"((r)[8]),  "=r"((r)[9]),  "=r"((r)[10]), "=r"((r)[11]), \
          "=r"((r)[12]), "=r"((r)[13]), "=r"((r)[14]), "=r"((r)[15]), \
          "=r"((r)[16]), "=r"((r)[17]), "=r"((r)[18]), "=r"((r)[19]), \
          "=r"((r)[20]), "=r"((r)[21]), "=r"((r)[22]), "=r"((r)[23]), \
          "=r"((r)[24]), "=r"((r)[25]), "=r"((r)[26]), "=r"((r)[27]), \
          "=r"((r)[28]), "=r"((r)[29]), "=r"((r)[30]), "=r"((r)[31]) \
        : "r"(tmem_addr))
#endif

// ===========================================================================
// fp32 -> (bf16 hi, bf16 lo) split
// ===========================================================================
__global__ void __launch_bounds__(256)
split_kernel(const float* __restrict__ x, __nv_bfloat16* __restrict__ hi,
             __nv_bfloat16* __restrict__ lo, int n4)
{
    int i = blockIdx.x * blockDim.x + threadIdx.x;
    if (i >= n4) return;
    float4 v = ((const float4*)x)[i];
    __nv_bfloat16 hx = __float2bfloat16_rn(v.x);
    __nv_bfloat16 hy = __float2bfloat16_rn(v.y);
    __nv_bfloat16 hz = __float2bfloat16_rn(v.z);
    __nv_bfloat16 hw = __float2bfloat16_rn(v.w);
    __nv_bfloat16 lx = __float2bfloat16_rn(v.x - __bfloat162float(hx));
    __nv_bfloat16 ly = __float2bfloat16_rn(v.y - __bfloat162float(hy));
    __nv_bfloat16 lz = __float2bfloat16_rn(v.z - __bfloat162float(hz));
    __nv_bfloat16 lw = __float2bfloat16_rn(v.w - __bfloat162float(hw));
    ((__nv_bfloat162*)hi)[2 * i]     = __nv_bfloat162(hx, hy);
    ((__nv_bfloat162*)hi)[2 * i + 1] = __nv_bfloat162(hz, hw);
    ((__nv_bfloat162*)lo)[2 * i]     = __nv_bfloat162(lx, ly);
    ((__nv_bfloat162*)lo)[2 * i + 1] = __nv_bfloat162(lz, lw);
}

// fp32 -> bf16 (plain convert)
__global__ void __launch_bounds__(256)
convert_bf_kernel(const float* __restrict__ x, __nv_bfloat16* __restrict__ y, int n4)
{
    int i = blockIdx.x * blockDim.x + threadIdx.x;
    if (i >= n4) return;
    float4 v = ((const float4*)x)[i];
    ((__nv_bfloat162*)y)[2 * i]     = __nv_bfloat162(__float2bfloat16_rn(v.x), __float2bfloat16_rn(v.y));
    ((__nv_bfloat162*)y)[2 * i + 1] = __nv_bfloat162(__float2bfloat16_rn(v.z), __float2bfloat16_rn(v.w));
}

// V [b*2048+key][h*64+d] fp32 -> VT [bh][d][key] bf16.  grid (16 keytiles, 64 bh), 128 thr.
__global__ void __launch_bounds__(128)
transpose_v_kernel(const float* __restrict__ V, __nv_bfloat16* __restrict__ VT)
{
    __shared__ __nv_bfloat16 tt[128][HDIM + 8];
    const int tid = threadIdx.x;
    const int kt = blockIdx.x, bh = blockIdx.y;
    const int b = bh >> 4, h = bh & 15;

    const float* src = V + ((size_t)(b * SEQ + kt * 128 + tid)) * DMODEL + h * HDIM;
#pragma unroll
    for (int c = 0; c < 16; c++) {
        float4 v = ((const float4*)src)[c];
        tt[tid][4 * c + 0] = __float2bfloat16_rn(v.x);
        tt[tid][4 * c + 1] = __float2bfloat16_rn(v.y);
        tt[tid][4 * c + 2] = __float2bfloat16_rn(v.z);
        tt[tid][4 * c + 3] = __float2bfloat16_rn(v.w);
    }
    __syncthreads();
    const int d = tid >> 1, half = tid & 1;
    __nv_bfloat16* dst = VT + ((size_t)bh * HDIM + d) * SEQ + kt * 128 + half * 64;
#pragma unroll
    for (int c = 0; c < 64; c++) dst[c] = tt[half * 64 + c][d];
}

// ===========================================================================
// GEMM: C = (Ahi+Alo) @ (Whi+Wlo)^T + bias (+resid). tcgen05 / SIMT fallback.
// ===========================================================================
#define GM_K        DMODEL
#define CHUNK       64
#define NCHUNK      (GM_K / CHUNK)           // 16
#define TILE_B      (128 * 128)
#define OFF_AHI     1024
#define OFF_ALO     (OFF_AHI + TILE_B)
#define OFF_WHI     (OFF_ALO + TILE_B)
#define OFF_WLO     (OFF_WHI + TILE_B)
#define GEMM_SMEM   (OFF_WLO + TILE_B)       // 66560

static constexpr uint32_t GEMM_IDESC =
    (1u << 4) | (1u << 7) | (1u << 10) | ((128u / 8u) << 17) | ((128u / 16u) << 24);

__global__ void __launch_bounds__(128)
gemm_tc_kernel(const __nv_bfloat16* __restrict__ Ahi, const __nv_bfloat16* __restrict__ Alo,
               const __nv_bfloat16* __restrict__ Whi, const __nv_bfloat16* __restrict__ Wlo,
               const float* __restrict__ bias, const float* __restrict__ resid,
               float* __restrict__ C)
{
    extern __shared__ char smem[];
    const int tid = threadIdx.x;
    const int bn = blockIdx.x * 128;
    const int bm = blockIdx.y * 128;

#if HAS_TCGEN05
    const uint32_t sbase = smem_u32(smem);
    const uint32_t mbar = sbase + 16;
    const int wid = tid >> 5, lid = tid & 31;

    if (wid == 0)
        asm volatile("tcgen05.alloc.cta_group::1.sync.aligned.shared::cta.b32 [%0], %1;"
                     :: "r"(sbase), "r"(128u) : "memory");
    if (tid == 0) mbar_init(mbar, 1);
    __syncthreads();
    uint32_t tmem;
    asm volatile("ld.shared.b32 %0, [%1];" : "=r"(tmem) : "r"(sbase));

    const int seg = tid & 7;
    const int r0 = tid >> 3;

    for (int c = 0; c < NCHUNK; ++c) {
        if (c > 0) mbar_wait(mbar, (c - 1) & 1);
        __syncthreads();

        const int kc = c * CHUNK;
#pragma unroll
        for (int s = 0; s < 8; ++s) {
            const int row = s * 16 + r0;
            uint32_t boff = (uint32_t)row * 128u + (uint32_t)seg * 16u;
            uint32_t sw = boff ^ ((boff >> 3) & 0x70u);
            const uint4* ga  = (const uint4*)(Ahi + (size_t)(bm + row) * GM_K + kc);
            const uint4* gal = (const uint4*)(Alo + (size_t)(bm + row) * GM_K + kc);
            const uint4* gw  = (const uint4*)(Whi + (size_t)(bn + row) * GM_K + kc);
            const uint4* gwl = (const uint4*)(Wlo + (size_t)(bn + row) * GM_K + kc);
            *(uint4*)(smem + OFF_AHI + sw) = ga[seg];
            *(uint4*)(smem + OFF_ALO + sw) = gal[seg];
            *(uint4*)(smem + OFF_WHI + sw) = gw[seg];
            *(uint4*)(smem + OFF_WLO + sw) = gwl[seg];
        }
        fence_proxy_async_shared();
        __syncthreads();

        if (wid == 0 && elect_one()) {
            const uint64_t dah = make_desc(sbase + OFF_AHI);
            const uint64_t dal = make_desc(sbase + OFF_ALO);
            const uint64_t dwh = make_desc(sbase + OFF_WHI);
            const uint64_t dwl = make_desc(sbase + OFF_WLO);
#pragma unroll
            for (int k = 0; k < 4; ++k)
                mma_bf16_ss(tmem, dah + k * 2, dwh + k * 2, GEMM_IDESC, (c > 0) || (k > 0));
#pragma unroll
            for (int k = 0; k < 4; ++k)
                mma_bf16_ss(tmem, dal + k * 2, dwh + k * 2, GEMM_IDESC, 1u);
#pragma unroll
            for (int k = 0; k < 4; ++k)
                mma_bf16_ss(tmem, dah + k * 2, dwl + k * 2, GEMM_IDESC, 1u);
            asm volatile("tcgen05.commit.cta_group::1.mbarrier::arrive::one.shared::cluster.b64 [%0];"
                         :: "r"(mbar) : "memory");
        }
    }

    mbar_wait(mbar, (NCHUNK - 1) & 1);
    asm volatile("tcgen05.fence::after_thread_sync;" ::: "memory");

    const int row = bm + wid * 32 + lid;
    float* crow = C + (size_t)row * DMODEL + bn;
    const float* rrow = resid ? resid + (size_t)row * DMODEL + bn : nullptr;
#pragma unroll
    for (int c0 = 0; c0 < 128; c0 += 32) {
        uint32_t dr[32];
        TCGEN05_LD_X32(dr, tmem + c0);
        asm volatile("tcgen05.wait::ld.sync.aligned;" ::: "memory");
#pragma unroll
        for (int j = 0; j < 32; j += 4) {
            float4 v;
            v.x = __uint_as_float(dr[j + 0]) + bias[bn + c0 + j + 0];
            v.y = __uint_as_float(dr[j + 1]) + bias[bn + c0 + j + 1];
            v.z = __uint_as_float(dr[j + 2]) + bias[bn + c0 + j + 2];
            v.w = __uint_as_float(dr[j + 3]) + bias[bn + c0 + j + 3];
            if (rrow) {
                float4 r = *(const float4*)(rrow + c0 + j);
                v.x += r.x; v.y += r.y; v.z += r.z; v.w += r.w;
            }
            *(float4*)(crow + c0 + j) = v;
        }
    }
    asm volatile("tcgen05.fence::before_thread_sync;" ::: "memory");
    __syncthreads();
    if (wid == 0) {
        asm volatile("tcgen05.relinquish_alloc_permit.cta_group::1.sync.aligned;" ::: "memory");
        asm volatile("tcgen05.dealloc.cta_group::1.sync.aligned.b32 %0, %1;" :: "r"(tmem), "r"(128u));
    }

#else  // ---------------- SIMT fallback ----------------
    float* As = (float*)smem;             // [16][128]
    float* Ws = (float*)(smem + 8192);    // [16][128]
    const int tr = tid >> 4;
    const int tc = tid & 15;

    float acc[16][8];
#pragma unroll
    for (int i = 0; i < 16; i++)
#pragma unroll
        for (int j = 0; j < 8; j++) acc[i][j] = 0.f;

    for (int k0 = 0; k0 < GM_K; k0 += 16) {
        __syncthreads();
        {
            const __nv_bfloat162* ah = (const __nv_bfloat162*)(Ahi + (size_t)(bm + tid) * GM_K + k0);
            const __nv_bfloat162* al = (const __nv_bfloat162*)(Alo + (size_t)(bm + tid) * GM_K + k0);
            const __nv_bfloat162* wh = (const __nv_bfloat162*)(Whi + (size_t)(bn + tid) * GM_K + k0);
            const __nv_bfloat162* wl = (const __nv_bfloat162*)(Wlo + (size_t)(bn + tid) * GM_K + k0);
#pragma unroll
            for (int p = 0; p < 8; p++) {
                float2 h = __bfloat1622float2(ah[p]);
                float2 l = __bfloat1622float2(al[p]);
                As[(2 * p) * 128 + tid]     = h.x + l.x;
                As[(2 * p + 1) * 128 + tid] = h.y + l.y;
                float2 wh2 = __bfloat1622float2(wh[p]);
                float2 wl2 = __bfloat1622float2(wl[p]);
                Ws[(2 * p) * 128 + tid]     = wh2.x + wl2.x;
                Ws[(2 * p + 1) * 128 + tid] = wh2.y + wl2.y;
            }
        }
        __syncthreads();
#pragma unroll
        for (int k = 0; k < 16; k++) {
            float b[8];
#pragma unroll
            for (int j = 0; j < 8; j++) b[j] = Ws[k * 128 + tc * 8 + j];
#pragma unroll
            for (int i = 0; i < 16; i++) {
                float a = As[k * 128 + tr * 16 + i];
#pragma unroll
                for (int j = 0; j < 8; j++) acc[i][j] += a * b[j];
            }
        }
    }

#pragma unroll
    for (int i = 0; i < 16; i++) {
        const int row = bm + tr * 16 + i;
        float* cp = C + (size_t)row * DMODEL + bn + tc * 8;
#pragma unroll
        for (int j = 0; j < 8; j++) {
            float v = acc[i][j] + bias[bn + tc * 8 + j];
            if (resid) v += resid[(size_t)row * DMODEL + bn + tc * 8 + j];
            cp[j] = v;
        }
    }
#endif
}

// ===========================================================================
// Attention.  tcgen05 flash path / SIMT f32x2 fallback.
// grid (16 qtiles, 64 bh), 128 threads.
// ===========================================================================
#define AT_OFF_QH   1024
#define AT_OFF_QL   (AT_OFF_QH + 16384)
#define AT_OFF_K    (AT_OFF_QL + 16384)
#define AT_OFF_VT   (AT_OFF_K + 16384)
#define AT_OFF_P    (AT_OFF_VT + 16384)
#define ATTN_SMEM   (AT_OFF_P + 32768)       // 99328

static constexpr uint32_t IDESC_QK =
    (1u << 4) | (1u << 7) | (1u << 10) | (16u << 17) | (8u << 24);   // M=128,N=128
static constexpr uint32_t IDESC_PV =
    (1u << 4) | (1u << 7) | (1u << 10) | (8u << 17) | (8u << 24);    // M=128,N=64

__global__ void __launch_bounds__(128)
attn_kernel(const __nv_bfloat16* __restrict__ Qhi, const __nv_bfloat16* __restrict__ Qlo,
            const __nv_bfloat16* __restrict__ Kbf, const __nv_bfloat16* __restrict__ VT,
            const float* __restrict__ Qf, const float* __restrict__ Kf,
            const float* __restrict__ Vf, float* __restrict__ O)
{
    extern __shared__ char smem[];
    const int tid = threadIdx.x;
    const int qtile = blockIdx.x;            // 0..15
    const int bh = blockIdx.y;               // 0..63
    const int b = bh >> 4, h = bh & 15;

#if HAS_TCGEN05
    const uint32_t sbase = smem_u32(smem);
    const uint32_t mbar = sbase + 16;
    const int wid = tid >> 5;

    if (wid == 0)
        asm volatile("tcgen05.alloc.cta_group::1.sync.aligned.shared::cta.b32 [%0], %1;"
                     :: "r"(sbase), "r"(256u) : "memory");
    if (tid == 0) mbar_init(mbar, 1);
    __syncthreads();
    uint32_t tmem;
    asm volatile("ld.shared.b32 %0, [%1];" : "=r"(tmem) : "r"(sbase));
    const uint32_t tmem_S = tmem;            // cols 0..127
    const uint32_t tmem_O = tmem + 128;      // cols 128..191

    // load Q tiles once: thread t -> q row t (128B contiguous)
    {
        const size_t qgrow = (size_t)(b * SEQ + qtile * 128 + tid) * DMODEL + h * HDIM;
        const uint4* gh = (const uint4*)(Qhi + qgrow);
        const uint4* gl = (const uint4*)(Qlo + qgrow);
#pragma unroll
        for (int c = 0; c < 8; c++) {
            uint32_t boff = (uint32_t)tid * 128u + c * 16u;
            uint32_t sw = boff ^ ((boff >> 3) & 0x70u);
            *(uint4*)(smem + AT_OFF_QH + sw) = gh[c];
            *(uint4*)(smem + AT_OFF_QL + sw) = gl[c];
        }
    }

    float m = -1e30f, l = 0.f, o[64];
#pragma unroll
    for (int d = 0; d < 64; d++) o[d] = 0.f;
    uint32_t ph = 0;

    for (int j0 = 0; j0 < SEQ / 128; ++j0) {
        // ---- load K tile (thread t -> key row t) ----
        {
            const uint4* ks = (const uint4*)(Kbf + (size_t)(b * SEQ + j0 * 128 + tid) * DMODEL + h * HDIM);
#pragma unroll
            for (int c = 0; c < 8; c++) {
                uint32_t boff = (uint32_t)tid * 128u + c * 16u;
                uint32_t sw = boff ^ ((boff >> 3) & 0x70u);
                *(uint4*)(smem + AT_OFF_K + sw) = ks[c];
            }
        }
        // ---- load VT tile (thread t -> d = t>>1, half = t&1) ----
        {
            const int d = tid >> 1, half = tid & 1;
            const uint4* vs = (const uint4*)(VT + ((size_t)bh * HDIM + d) * SEQ + j0 * 128 + half * 64);
#pragma unroll
            for (int c = 0; c < 8; c++) {
                int key = half * 64 + c * 8;
                uint32_t atom = (uint32_t)(d >> 3) + (uint32_t)(key >> 6) * 8u;
                uint32_t boff = atom * 1024u + (uint32_t)(d & 7) * 128u + (uint32_t)(key & 63) * 2u;
                uint32_t sw = boff ^ ((boff >> 3) & 0x70u);
                *(uint4*)(smem + AT_OFF_VT + sw) = vs[c];
            }
        }
        fence_proxy_async_shared();
        __syncthreads();

        // ---- S = Qhi*K^T + Qlo*K^T ----
        if (wid == 0 && elect_one()) {
            const uint64_t dqh = make_desc(sbase + AT_OFF_QH);
            const uint64_t dql = make_desc(sbase + AT_OFF_QL);
            const uint64_t dk  = make_desc(sbase + AT_OFF_K);
#pragma unroll
            for (int k = 0; k < 4; ++k)
                mma_bf16_ss(tmem_S, dqh + k * 2, dk + k * 2, IDESC_QK, k > 0);
#pragma unroll
            for (int k = 0; k < 4; ++k)
                mma_bf16_ss(tmem_S, dql + k * 2, dk + k * 2, IDESC_QK, 1u);
            asm volatile("tcgen05.commit.cta_group::1.mbarrier::arrive::one.shared::cluster.b64 [%0];"
                         :: "r"(mbar) : "memory");
        }
        mbar_wait(mbar, ph); ph ^= 1;
        asm volatile("tcgen05.fence::after_thread_sync;" ::: "memory");

        // ---- read S row (thread = q row), softmax ----
        uint32_t sr[128];
        TCGEN05_LD_X32(sr + 0,  tmem_S + 0);
        TCGEN05_LD_X32(sr + 32, tmem_S + 32);
        TCGEN05_LD_X32(sr + 64, tmem_S + 64);
        TCGEN05_LD_X32(sr + 96, tmem_S + 96);
        asm volatile("tcgen05.wait::ld.sync.aligned;" ::: "memory");

        float mx = m;
#pragma unroll
        for (int j = 0; j < 128; j++)
            mx = fmaxf(mx, __uint_as_float(sr[j]) * 0.125f);
        const float c = __expf(m - mx);
        m = mx;

        float lsum = 0.f;
        uint32_t pk[64];
#pragma unroll
        for (int j = 0; j < 64; j++) {
            float p0 = __expf(__uint_as_float(sr[2 * j])     * 0.125f - mx);
            float p1 = __expf(__uint_as_float(sr[2 * j + 1]) * 0.125f - mx);
            lsum += p0 + p1;
            __nv_bfloat162 pb = __floats2bfloat162_rn(p0, p1);
            pk[j] = *(uint32_t*)&pb;
        }
        l = l * c + lsum;

        // ---- store P (row tid, all 128 bf16 cols, blocked SW128 atoms) ----
#pragma unroll
        for (int s = 0; s < 16; s++) {
            int col = s * 8;
            uint32_t atom = (uint32_t)(tid >> 3) + (uint32_t)(col >> 6) * 16u;
            uint32_t boff = atom * 1024u + (uint32_t)(tid & 7) * 128u + (uint32_t)(col & 63) * 2u;
            uint32_t sw = boff ^ ((boff >> 3) & 0x70u);
            uint4 val = make_uint4(pk[4 * s], pk[4 * s + 1], pk[4 * s + 2], pk[4 * s + 3]);
            *(uint4*)(smem + AT_OFF_P + sw) = val;
        }
        fence_proxy_async_shared();
        __syncthreads();

        // ---- dO = P * V^T-tile ----
        if (wid == 0 && elect_one()) {
            const uint64_t dp = make_desc(sbase + AT_OFF_P);
            const uint64_t dv = make_desc(sbase + AT_OFF_VT);
#pragma unroll
            for (int st = 0; st < 8; ++st) {
                uint64_t po = (st < 4) ? (uint64_t)(st * 2) : (uint64_t)(1024 + (st - 4) * 2);
                uint64_t vo = (st < 4) ? (uint64_t)(st * 2) : (uint64_t)(512 + (st - 4) * 2);
                mma_bf16_ss(tmem_O, dp + po, dv + vo, IDESC_PV, st > 0);
            }
            asm volatile("tcgen05.commit.cta_group::1.mbarrier::arrive::one.shared::cluster.b64 [%0];"
                         :: "r"(mbar) : "memory");
        }
        mbar_wait(mbar, ph); ph ^= 1;
        asm volatile("tcgen05.fence::after_thread_sync;" ::: "memory");

        uint32_t orr[64];
        TCGEN05_LD_X32(orr + 0,  tmem_O + 0);
        TCGEN05_LD_X32(orr + 32, tmem_O + 32);
        asm volatile("tcgen05.wait::ld.sync.aligned;" ::: "memory");
#pragma unroll
        for (int d = 0; d < 64; d++)
            o[d] = o[d] * c + __uint_as_float(orr[d]);
        __syncthreads();
    }

    // epilogue
    const float inv = 1.f / l;
    float* optr = O + (size_t)(b * SEQ + qtile * 128 + tid) * DMODEL + h * HDIM;
#pragma unroll
    for (int i = 0; i < 16; i++) {
        ((float4*)optr)[i] = make_float4(o[4 * i] * inv, o[4 * i + 1] * inv,
                                         o[4 * i + 2] * inv, o[4 * i + 3] * inv);
    }
    asm volatile("tcgen05.fence::before_thread_sync;" ::: "memory");
    __syncthreads();
    if (wid == 0) {
        asm volatile("tcgen05.relinquish_alloc_permit.cta_group::1.sync.aligned;" ::: "memory");
        asm volatile("tcgen05.dealloc.cta_group::1.sync.aligned.b32 %0, %1;" :: "r"(tmem), "r"(256u));
    }

#else  // ---------------- SIMT f32x2 fallback (uses fp32 Q/K/V) ----------------
    float4* Ks4 = (float4*)smem;
    float4* Vs4 = Ks4 + 64 * 16;
    const int qrow = qtile * 128 + tid;

    const float* qptr = Qf + ((size_t)(b * SEQ + qrow)) * DMODEL + h * HDIM;
    unsigned long long qp[32], op[32];
#pragma unroll
    for (int i = 0; i < 16; i++) {
        float4 t = ((const float4*)qptr)[i];
        qp[2 * i]     = pk2(t.x, t.y);
        qp[2 * i + 1] = pk2(t.z, t.w);
    }
#pragma unroll
    for (int i = 0; i < 32; i++) op[i] = 0ull;

    float m = -1e30f, l = 0.f;
    const float* kbase = Kf + (size_t)b * SEQ * DMODEL + h * HDIM;
    const float* vbase = Vf + (size_t)b * SEQ * DMODEL + h * HDIM;
    const ulonglong2* Ku = (const ulonglong2*)Ks4;
    const ulonglong2* Vu = (const ulonglong2*)Vs4;

    for (int j0 = 0; j0 < SEQ; j0 += 64) {
        __syncthreads();
        for (int i = tid; i < 64 * 16; i += 128) {
            const int r = i >> 4, cc = i & 15;
            Ks4[i] = ((const float4*)(kbase + (size_t)(j0 + r) * DMODEL))[cc];
            Vs4[i] = ((const float4*)(vbase + (size_t)(j0 + r) * DMODEL))[cc];
        }
        __syncthreads();

        for (int j = 0; j < 64; j++) {
            unsigned long long a0 = 0ull, a1 = 0ull;
#pragma unroll
            for (int d4 = 0; d4 < 16; d4++) {
                ulonglong2 kk = Ku[j * 16 + d4];
                a0 = ffma2(qp[2 * d4], kk.x, a0);
                a1 = ffma2(qp[2 * d4 + 1], kk.y, a1);
            }
            float sx, sy, sz, sw;
            unpk2(a0, sx, sy); unpk2(a1, sz, sw);
            float s = ((sx + sy) + (sz + sw)) * 0.125f;

            if (s > m) {
                float cc2 = __expf(m - s);
                l *= cc2;
                unsigned long long c2 = pk2(cc2, cc2);
#pragma unroll
                for (int i = 0; i < 32; i++) op[i] = fmul2(op[i], c2);
                m = s;
            }
            float p = __expf(s - m);
            l += p;
            unsigned long long p2 = pk2(p, p);
#pragma unroll
            for (int d4 = 0; d4 < 16; d4++) {
                ulonglong2 vv = Vu[j * 16 + d4];
                op[2 * d4]     = ffma2(p2, vv.x, op[2 * d4]);
                op[2 * d4 + 1] = ffma2(p2, vv.y, op[2 * d4 + 1]);
            }
        }
    }

    const float inv = 1.f / l;
    float* optr = O + ((size_t)(b * SEQ + qrow)) * DMODEL + h * HDIM;
#pragma unroll
    for (int i = 0; i < 16; i++) {
        float ox, oy, oz, ow;
        unpk2(op[2 * i], ox, oy); unpk2(op[2 * i + 1], oz, ow);
        ((float4*)optr)[i] = make_float4(ox * inv, oy * inv, oz * inv, ow * inv);
    }
#endif
}

// ===========================================================================
// LayerNorm over rows of 1024
// ===========================================================================
__global__ void __launch_bounds__(256)
ln_kernel(const float* __restrict__ Y, const float* __restrict__ gamma,
          const float* __restrict__ beta, float* __restrict__ out)
{
    __shared__ float red[8];
    __shared__ float bcast;

    const int row = blockIdx.x;
    const int tid = threadIdx.x;
    const float4 v = ((const float4*)(Y + (size_t)row * DMODEL))[tid];

    float s = v.x + v.y + v.z + v.w;
#pragma unroll
    for (int off = 16; off; off >>= 1) s += __shfl_xor_sync(0xffffffffu, s, off);
    if ((tid & 31) == 0) red[tid >> 5] = s;
    __syncthreads();
    if (tid == 0) {
        float t = 0.f;
#pragma unroll
        for (int i = 0; i < 8; i++) t += red[i];
        bcast = t * (1.f / 1024.f);
    }
    __syncthreads();
    const float mean = bcast;

    const float dx = v.x - mean, dy = v.y - mean, dz = v.z - mean, dw = v.w - mean;
    float ss = dx * dx + dy * dy + dz * dz + dw * dw;
#pragma unroll
    for (int off = 16; off; off >>= 1) ss += __shfl_xor_sync(0xffffffffu, ss, off);
    __syncthreads();
    if ((tid & 31) == 0) red[tid >> 5] = ss;
    __syncthreads();
    if (tid == 0) {
        float t = 0.f;
#pragma unroll
        for (int i = 0; i < 8; i++) t += red[i];
        bcast = rsqrtf(t * (1.f / 1024.f) + 1e-12f);
    }
    __syncthreads();
    const float inv = bcast;

    const float4 g = ((const float4*)gamma)[tid];
    const float4 bb = ((const float4*)beta)[tid];
    float4 o = make_float4(dx * inv * g.x + bb.x, dy * inv * g.y + bb.y,
                           dz * inv * g.z + bb.z, dw * inv * g.w + bb.w);
    ((float4*)(out + (size_t)row * DMODEL))[tid] = o;
}

// ===========================================================================
extern "C" void kernel_launch(void* const* d_in, const int* in_sizes, int n_in,
                              void* d_out, int out_size)
{
    const float* X     = (const float*)d_in[0];
    const float* Wq    = (const float*)d_in[1];
    const float* bq    = (const float*)d_in[2];
    const float* Wk    = (const float*)d_in[3];
    const float* bk    = (const float*)d_in[4];
    const float* Wv    = (const float*)d_in[5];
    const float* bv    = (const float*)d_in[6];
    const float* Wo    = (const float*)d_in[7];
    const float* bo    = (const float*)d_in[8];
    const float* gamma = (const float*)d_in[9];
    const float* beta  = (const float*)d_in[10];
    float* out = (float*)d_out;

    float *Qb, *Kb, *Vb, *Ob;
    __nv_bfloat16 *Ahi, *Alo, *Whi, *Wlo, *Kbf, *VTb;
    cudaGetSymbolAddress((void**)&Qb, g_Q);
    cudaGetSymbolAddress((void**)&Kb, g_K);
    cudaGetSymbolAddress((void**)&Vb, g_V);
    cudaGetSymbolAddress((void**)&Ob, g_AO);
    cudaGetSymbolAddress((void**)&Ahi, g_Ahi);
    cudaGetSymbolAddress((void**)&Alo, g_Alo);
    cudaGetSymbolAddress((void**)&Whi, g_Whi);
    cudaGetSymbolAddress((void**)&Wlo, g_Wlo);
    cudaGetSymbolAddress((void**)&Kbf, g_Kbf);
    cudaGetSymbolAddress((void**)&VTb, g_VT);

    cudaFuncSetAttribute(gemm_tc_kernel, cudaFuncAttributeMaxDynamicSharedMemorySize, GEMM_SMEM);
    cudaFuncSetAttribute(attn_kernel, cudaFuncAttributeMaxDynamicSharedMemorySize, ATTN_SMEM);

    const int nX4 = ROWS * DMODEL / 4;      // 2M
    const int nW4 = DMODEL * DMODEL / 4;    // 256K
    dim3 gemm_grid(DMODEL / 128, ROWS / 128);   // (8, 64)

    // split activations X
    split_kernel<<<(nX4 + 255) / 256, 256>>>(X, Ahi, Alo, nX4);

    // Q = X @ Wq^T + bq
    split_kernel<<<(nW4 + 255) / 256, 256>>>(Wq, Whi, Wlo, nW4);
    gemm_tc_kernel<<<gemm_grid, 128, GEMM_SMEM>>>(Ahi, Alo, Whi, Wlo, bq, nullptr, Qb);
    // K
    split_kernel<<<(nW4 + 255) / 256, 256>>>(Wk, Whi, Wlo, nW4);
    gemm_tc_kernel<<<gemm_grid, 128, GEMM_SMEM>>>(Ahi, Alo, Whi, Wlo, bk, nullptr, Kb);
    // V
    split_kernel<<<(nW4 + 255) / 256, 256>>>(Wv, Whi, Wlo, nW4);
    gemm_tc_kernel<<<gemm_grid, 128, GEMM_SMEM>>>(Ahi, Alo, Whi, Wlo, bv, nullptr, Vb);

    // attention operand prep: Q split (overwrites X split), K->bf16, V->V^T bf16
    split_kernel<<<(nX4 + 255) / 256, 256>>>(Qb, Ahi, Alo, nX4);
    convert_bf_kernel<<<(nX4 + 255) / 256, 256>>>(Kb, Kbf, nX4);
    transpose_v_kernel<<<dim3(SEQ / 128, BATCH * NHEAD), 128>>>(Vb, VTb);

    // attention
    attn_kernel<<<dim3(SEQ / 128, BATCH * NHEAD), 128, ATTN_SMEM>>>(
        Ahi, Alo, Kbf, VTb, Qb, Kb, Vb, Ob);

    // Y = AO @ Wo^T + bo + X   (into Qb, reused as Y scratch)
    split_kernel<<<(nX4 + 255) / 256, 256>>>(Ob, Ahi, Alo, nX4);
    split_kernel<<<(nW4 + 255) / 256, 256>>>(Wo, Whi, Wlo, nW4);
    gemm_tc_kernel<<<gemm_grid, 128, GEMM_SMEM>>>(Ahi, Alo, Whi, Wlo, bo, X, Qb);

    ln_kernel<<<ROWS, 256>>>(Qb, gamma, beta, out);
}